// round 2
// baseline (speedup 1.0000x reference)
#include <cuda_runtime.h>
#include <cuda_bf16.h>

// Problem constants (fixed shapes)
#define N_NODES 50000
#define N_EDGES 600000
#define EE_MAX  (N_NODES + N_EDGES)   // edges + self loops = 650000
#define DIM     128
#define HEADS   4
#define NEG_SLOPE 0.2f

// ---------------- scratch (static device globals; no allocation) -------------
__device__ float g_h    [(long long)N_NODES * DIM];   // h = X @ W (both layers)
__device__ float g_out1 [(long long)N_NODES * DIM];   // layer-1 aggregated output
__device__ float g_als  [N_NODES * HEADS];
__device__ float g_ald  [N_NODES * HEADS];
__device__ int   g_emax [N_NODES * HEADS];
__device__ float g_denom[N_NODES * HEADS];
__device__ float g_ex   [(long long)EE_MAX * HEADS];  // per-edge logits then exp

// order-preserving float<->int transform for atomicMax on signed floats
__device__ __forceinline__ int   f2ord(float f){ int i = __float_as_int(f); return i < 0 ? (i ^ 0x7FFFFFFF) : i; }
__device__ __forceinline__ float ord2f(int i){ return __int_as_float(i < 0 ? (i ^ 0x7FFFFFFF) : i); }
#define ORD_NEG_INF ((int)0x807FFFFF)   // f2ord(-inf)

// ---------------- GEMM (+ fused attention logit reduction) ------------------
// One block = 8 node rows, 128 threads (thread = output channel).
template<int H>
__global__ void k_gemm_al(const float* __restrict__ X, const float* __restrict__ W,
                          const float* __restrict__ a_s, const float* __restrict__ a_d,
                          float* __restrict__ Hout, float* __restrict__ als,
                          float* __restrict__ ald, int N)
{
    __shared__ float xs[8][DIM];
    __shared__ float red_s[8][4], red_d[8][4];
    const int c  = threadIdx.x;           // 0..127
    const int n0 = blockIdx.x * 8;

    #pragma unroll
    for (int r = 0; r < 8; r++) {
        int n = n0 + r;
        xs[r][c] = (n < N) ? X[(long long)n * DIM + c] : 0.f;
    }
    __syncthreads();

    float acc[8];
    #pragma unroll
    for (int r = 0; r < 8; r++) acc[r] = 0.f;

    #pragma unroll 8
    for (int k = 0; k < DIM; k++) {
        float w = W[k * DIM + c];
        #pragma unroll
        for (int r = 0; r < 8; r++) acc[r] = fmaf(xs[r][k], w, acc[r]);
    }

    const float as = a_s[c];
    const float ad = a_d[c];
    const int lane = c & 31, warp = c >> 5;

    #pragma unroll
    for (int r = 0; r < 8; r++) {
        int n = n0 + r;
        if (n < N) Hout[(long long)n * DIM + c] = acc[r];
        float vs = acc[r] * as;
        float vd = acc[r] * ad;
        #pragma unroll
        for (int o = 16; o > 0; o >>= 1) {
            vs += __shfl_xor_sync(0xffffffffu, vs, o);
            vd += __shfl_xor_sync(0xffffffffu, vd, o);
        }
        if (H == 4) {
            if (lane == 0 && n < N) { als[n * 4 + warp] = vs; ald[n * 4 + warp] = vd; }
        } else {
            if (lane == 0) { red_s[r][warp] = vs; red_d[r][warp] = vd; }
        }
    }
    if (H == 1) {
        __syncthreads();
        if (c < 8) {
            int n = n0 + c;
            if (n < N) {
                als[n] = red_s[c][0] + red_s[c][1] + red_s[c][2] + red_s[c][3];
                ald[n] = red_d[c][0] + red_d[c][1] + red_d[c][2] + red_d[c][3];
            }
        }
    }
}

// ---------------- init helpers ----------------
__global__ void k_init_soft(int* __restrict__ emax, float* __restrict__ denom, int cnt)
{
    int i = blockIdx.x * blockDim.x + threadIdx.x;
    if (i < cnt) { emax[i] = ORD_NEG_INF; denom[i] = 0.f; }
}
__global__ void k_zero(float* __restrict__ p, long long cnt)
{
    long long i = (long long)blockIdx.x * blockDim.x + threadIdx.x;
    if (i < cnt) p[i] = 0.f;
}

// ---------------- edge pass A: leaky-relu logits + segment max ----------------
// edge_index is int32 (JAX canonicalizes int64 -> int32 without x64 enabled)
template<int H>
__global__ void k_logits(const int* __restrict__ ei, int E, int EE,
                         const float* __restrict__ als, const float* __restrict__ ald,
                         float* __restrict__ exbuf, int* __restrict__ emax)
{
    int e = blockIdx.x * blockDim.x + threadIdx.x;
    if (e >= EE) return;
    int src, dst;
    if (e < E) { src = ei[e]; dst = ei[E + e]; } else { src = dst = e - E; }

    if (H == 4) {
        float4 s = *(const float4*)(als + (long long)src * 4);
        float4 d = *(const float4*)(ald + (long long)dst * 4);
        float v[4] = { s.x + d.x, s.y + d.y, s.z + d.z, s.w + d.w };
        #pragma unroll
        for (int h = 0; h < 4; h++) {
            float vv = v[h] > 0.f ? v[h] : NEG_SLOPE * v[h];
            exbuf[(long long)e * 4 + h] = vv;
            atomicMax(&emax[dst * 4 + h], f2ord(vv));
        }
    } else {
        float v = als[src] + ald[dst];
        v = v > 0.f ? v : NEG_SLOPE * v;
        exbuf[e] = v;
        atomicMax(&emax[dst], f2ord(v));
    }
}

// ---------------- edge pass B: exp + segment sum ----------------
template<int H>
__global__ void k_expsum(const int* __restrict__ ei, int E, int EE,
                         float* __restrict__ exbuf, const int* __restrict__ emax,
                         float* __restrict__ denom)
{
    int e = blockIdx.x * blockDim.x + threadIdx.x;
    if (e >= EE) return;
    int dst;
    if (e < E) { dst = ei[E + e]; } else { dst = e - E; }

    if (H == 4) {
        #pragma unroll
        for (int h = 0; h < 4; h++) {
            float v  = exbuf[(long long)e * 4 + h];
            float m  = ord2f(emax[dst * 4 + h]);
            float ex = __expf(v - m);
            exbuf[(long long)e * 4 + h] = ex;
            atomicAdd(&denom[dst * 4 + h], ex);
        }
    } else {
        float v  = exbuf[e];
        float m  = ord2f(emax[dst]);
        float ex = __expf(v - m);
        exbuf[e] = ex;
        atomicAdd(&denom[dst], ex);
    }
}

// ---------------- edge pass C: alpha-weighted scatter (vector RED) ----------------
// One warp per edge: lane handles 4 channels (float4), red.global.add.v4.f32.
template<int H>
__global__ void k_scatter(const int* __restrict__ ei, int E, int EE,
                          const float* __restrict__ hbuf, const float* __restrict__ exbuf,
                          const float* __restrict__ denom, float* __restrict__ out)
{
    int warp_in_block = threadIdx.x >> 5;
    int e = blockIdx.x * (blockDim.x >> 5) + warp_in_block;
    if (e >= EE) return;
    int lane = threadIdx.x & 31;

    int src, dst;
    if (e < E) { src = ei[e]; dst = ei[E + e]; } else { src = dst = e - E; }

    int c0 = lane * 4;
    float4 hv = *(const float4*)(hbuf + (long long)src * DIM + c0);

    float alpha;
    if (H == 4) {
        int head = lane >> 3;                 // c0/32
        float ex  = exbuf[(long long)e * 4 + head];
        float den = denom[dst * 4 + head];
        alpha = ex / (den + 1e-16f);
    } else {
        alpha = exbuf[e] / (denom[dst] + 1e-16f);
    }

    float vx = hv.x * alpha, vy = hv.y * alpha, vz = hv.z * alpha, vw = hv.w * alpha;
    float* addr = out + (long long)dst * DIM + c0;
    asm volatile("red.global.add.v4.f32 [%0], {%1, %2, %3, %4};"
                 :: "l"(addr), "f"(vx), "f"(vy), "f"(vz), "f"(vw) : "memory");
}

// ---------------- elementwise epilogues ----------------
__global__ void k_bias_elu(float* __restrict__ p, const float* __restrict__ b, long long cnt)
{
    long long i = (long long)blockIdx.x * blockDim.x + threadIdx.x;
    if (i < cnt) {
        float v = p[i] + b[(int)(i & (DIM - 1))];
        p[i] = v > 0.f ? v : expm1f(v);
    }
}
__global__ void k_bias_add(float* __restrict__ p, const float* __restrict__ b, long long cnt)
{
    long long i = (long long)blockIdx.x * blockDim.x + threadIdx.x;
    if (i < cnt) p[i] += b[(int)(i & (DIM - 1))];
}

// ---------------- launch ----------------
extern "C" void kernel_launch(void* const* d_in, const int* in_sizes, int n_in,
                              void* d_out, int out_size)
{
    const float* x   = (const float*)d_in[0];
    const int*   ei  = (const int*)d_in[1];     // int32 edge_index [2, E]
    const float* W1  = (const float*)d_in[2];
    const float* as1 = (const float*)d_in[3];
    const float* ad1 = (const float*)d_in[4];
    const float* b1  = (const float*)d_in[5];
    const float* W2  = (const float*)d_in[6];
    const float* as2 = (const float*)d_in[7];
    const float* ad2 = (const float*)d_in[8];
    const float* b2  = (const float*)d_in[9];
    float*       out = (float*)d_out;

    const int N  = in_sizes[0] / DIM;
    const int E  = in_sizes[1] / 2;
    const int EE = E + N;
    const long long ND = (long long)N * DIM;

    float *h, *out1, *als, *ald, *denom, *ex;
    int   *emax;
    cudaGetSymbolAddress((void**)&h,     g_h);
    cudaGetSymbolAddress((void**)&out1,  g_out1);
    cudaGetSymbolAddress((void**)&als,   g_als);
    cudaGetSymbolAddress((void**)&ald,   g_ald);
    cudaGetSymbolAddress((void**)&emax,  g_emax);
    cudaGetSymbolAddress((void**)&denom, g_denom);
    cudaGetSymbolAddress((void**)&ex,    g_ex);

    const int TB = 256;
    dim3 gE((unsigned)((EE + TB - 1) / TB));
    dim3 gEW((unsigned)((EE + 7) / 8));          // 8 warps per block of 256
    dim3 gND((unsigned)((ND + TB - 1) / TB));

    // ---------------- layer 1 (H = 4) ----------------
    k_gemm_al<4><<<(N + 7) / 8, 128>>>(x, W1, as1, ad1, h, als, ald, N);
    k_init_soft<<<(N * 4 + TB - 1) / TB, TB>>>(emax, denom, N * 4);
    k_zero<<<gND, TB>>>(out1, ND);
    k_logits<4><<<gE, TB>>>(ei, E, EE, als, ald, ex, emax);
    k_expsum<4><<<gE, TB>>>(ei, E, EE, ex, emax, denom);
    k_scatter<4><<<gEW, TB>>>(ei, E, EE, h, ex, denom, out1);
    k_bias_elu<<<gND, TB>>>(out1, b1, ND);

    // ---------------- layer 2 (H = 1) ----------------
    k_gemm_al<1><<<(N + 7) / 8, 128>>>(out1, W2, as2, ad2, h, als, ald, N);
    k_init_soft<<<(N + TB - 1) / TB, TB>>>(emax, denom, N);
    k_zero<<<gND, TB>>>(out, ND);
    k_logits<1><<<gE, TB>>>(ei, E, EE, als, ald, ex, emax);
    k_expsum<1><<<gE, TB>>>(ei, E, EE, ex, emax, denom);
    k_scatter<1><<<gEW, TB>>>(ei, E, EE, h, ex, denom, out);
    k_bias_add<<<gND, TB>>>(out, b2, ND);
}

// round 3
// speedup vs baseline: 1.4904x; 1.4904x over previous
#include <cuda_runtime.h>
#include <cuda_bf16.h>
#include <math_constants.h>

#define N_NODES 50000
#define N_EDGES 600000
#define EE_MAX  (N_NODES + N_EDGES)
#define DIM     128
#define HEADS   4
#define NEG_SLOPE 0.2f

// ---------------- scratch (static device globals) ----------------
__device__ float g_h    [(long long)N_NODES * DIM];
__device__ float g_out1 [(long long)N_NODES * DIM];
__device__ float g_als  [N_NODES * HEADS];
__device__ float g_ald  [N_NODES * HEADS];
__device__ int   g_deg  [N_NODES];
__device__ int   g_rowptr[N_NODES + 1];
__device__ int   g_fill [N_NODES];
__device__ int   g_csr  [EE_MAX];

// ---------------- packed fp32x2 helpers ----------------
__device__ __forceinline__ void ffma2(unsigned long long& acc, unsigned long long a,
                                      unsigned long long b)
{
    asm("fma.rn.f32x2 %0, %1, %2, %0;" : "+l"(acc) : "l"(a), "l"(b));
}
__device__ __forceinline__ unsigned long long splat2(float x)
{
    unsigned long long r;
    asm("mov.b64 %0, {%1, %1};" : "=l"(r) : "f"(x));
    return r;
}
__device__ __forceinline__ void unpack2(unsigned long long v, float& a, float& b)
{
    asm("mov.b64 {%0, %1}, %2;" : "=f"(a), "=f"(b) : "l"(v));
}

// ---------------- GEMM + fused attention-logit reduction ----------------
// Block: 128 threads = 4 warps, covers 16 rows x 128 channels.
// Thread: cg = tid&31 -> channels c0=4*cg..+3 ; rs = tid>>5 -> rows rs*4..+3.
// Accumulators packed as channel-pairs (f32x2).
template<int H>
__global__ void __launch_bounds__(128) k_gemm_al(
    const float* __restrict__ X, const float* __restrict__ W,
    const float* __restrict__ a_s, const float* __restrict__ a_d,
    float* __restrict__ Hout, float* __restrict__ als, float* __restrict__ ald, int N)
{
    __shared__ float xs[16][DIM];
    const int tid = threadIdx.x;
    const int cg  = tid & 31;
    const int rs  = tid >> 5;
    const int c0  = cg * 4;
    const int n0  = blockIdx.x * 16;

    // load 16 rows of X into smem (float4)
    for (int idx = tid; idx < 16 * (DIM / 4); idx += 128) {
        int r  = idx >> 5;           // 0..15
        int cc = (idx & 31) * 4;
        int n  = n0 + r;
        float4 v = make_float4(0.f, 0.f, 0.f, 0.f);
        if (n < N) v = *(const float4*)(X + (long long)n * DIM + cc);
        *(float4*)&xs[r][cc] = v;
    }
    __syncthreads();

    unsigned long long acc[4][2];
    #pragma unroll
    for (int r = 0; r < 4; r++) { acc[r][0] = 0ull; acc[r][1] = 0ull; }

    #pragma unroll 4
    for (int k = 0; k < DIM; k += 4) {
        // W rows k..k+3, channels c0..c0+3 (each as 2 packed pairs)
        ulonglong2 w0 = *(const ulonglong2*)(W + (k + 0) * DIM + c0);
        ulonglong2 w1 = *(const ulonglong2*)(W + (k + 1) * DIM + c0);
        ulonglong2 w2 = *(const ulonglong2*)(W + (k + 2) * DIM + c0);
        ulonglong2 w3 = *(const ulonglong2*)(W + (k + 3) * DIM + c0);
        #pragma unroll
        for (int r = 0; r < 4; r++) {
            float4 xv = *(const float4*)&xs[rs * 4 + r][k];
            unsigned long long x0 = splat2(xv.x), x1 = splat2(xv.y);
            unsigned long long x2 = splat2(xv.z), x3 = splat2(xv.w);
            ffma2(acc[r][0], w0.x, x0); ffma2(acc[r][1], w0.y, x0);
            ffma2(acc[r][0], w1.x, x1); ffma2(acc[r][1], w1.y, x1);
            ffma2(acc[r][0], w2.x, x2); ffma2(acc[r][1], w2.y, x2);
            ffma2(acc[r][0], w3.x, x3); ffma2(acc[r][1], w3.y, x3);
        }
    }

    const float4 as4 = *(const float4*)(a_s + c0);
    const float4 ad4 = *(const float4*)(a_d + c0);

    #pragma unroll
    for (int r = 0; r < 4; r++) {
        int n = n0 + rs * 4 + r;
        float a0, a1, a2, a3;
        unpack2(acc[r][0], a0, a1);
        unpack2(acc[r][1], a2, a3);
        if (n < N) {
            float4 o = make_float4(a0, a1, a2, a3);
            *(float4*)(Hout + (long long)n * DIM + c0) = o;
        }
        float ss = a0 * as4.x + a1 * as4.y + a2 * as4.z + a3 * as4.w;
        float sd = a0 * ad4.x + a1 * ad4.y + a2 * ad4.z + a3 * ad4.w;
        #pragma unroll
        for (int o = (H == 4 ? 4 : 16); o > 0; o >>= 1) {
            ss += __shfl_xor_sync(0xffffffffu, ss, o);
            sd += __shfl_xor_sync(0xffffffffu, sd, o);
        }
        if (H == 4) {
            if ((cg & 7) == 0 && n < N) {
                int hh = cg >> 3;
                als[n * 4 + hh] = ss;
                ald[n * 4 + hh] = sd;
            }
        } else {
            if (cg == 0 && n < N) { als[n] = ss; ald[n] = sd; }
        }
    }
}

// ---------------- CSR build ----------------
__global__ void k_deg_init(int* __restrict__ deg, int N)
{
    int i = blockIdx.x * blockDim.x + threadIdx.x;
    if (i < N) deg[i] = 1;   // self-loop pre-counted
}
__global__ void k_deg(const int* __restrict__ ei, int E, int* __restrict__ deg)
{
    int e = blockIdx.x * blockDim.x + threadIdx.x;
    if (e < E) atomicAdd(&deg[ei[E + e]], 1);
}
__global__ void k_scan(const int* __restrict__ deg, int* __restrict__ rowptr,
                       int* __restrict__ fill, int N)
{
    __shared__ int ssum[1024];
    int t = threadIdx.x;
    int strip = (N + 1023) / 1024;
    int lo = t * strip, hi = min(lo + strip, N);
    int s = 0;
    for (int i = lo; i < hi; i++) s += deg[i];
    ssum[t] = s;
    __syncthreads();
    for (int off = 1; off < 1024; off <<= 1) {
        int v = (t >= off) ? ssum[t - off] : 0;
        __syncthreads();
        ssum[t] += v;
        __syncthreads();
    }
    int base = (t == 0) ? 0 : ssum[t - 1];
    for (int i = lo; i < hi; i++) { rowptr[i] = base; fill[i] = base; base += deg[i]; }
    if (t == 1023) rowptr[N] = ssum[1023];
}
__global__ void k_fill(const int* __restrict__ ei, int E, int EE,
                       int* __restrict__ fill, int* __restrict__ csr)
{
    int e = blockIdx.x * blockDim.x + threadIdx.x;
    if (e >= EE) return;
    int src, dst;
    if (e < E) { src = ei[e]; dst = ei[E + e]; } else { src = dst = e - E; }
    int pos = atomicAdd(&fill[dst], 1);
    csr[pos] = src;
}

// ---------------- fused gather aggregation (softmax + weighted sum + bias [+ELU]) ---
// One warp per destination node. Lane -> 4 channels (c0 = lane*4).
template<int H, bool ELU>
__global__ void k_aggregate(const int* __restrict__ rowptr, const int* __restrict__ csr,
                            const float* __restrict__ als, const float* __restrict__ ald,
                            const float* __restrict__ hbuf, const float* __restrict__ bias,
                            float* __restrict__ out, int N)
{
    int gwarp = (blockIdx.x * blockDim.x + threadIdx.x) >> 5;
    if (gwarp >= N) return;
    const int lane = threadIdx.x & 31;
    const int head = (H == 4) ? (lane >> 3) : 0;
    const int c0   = lane * 4;

    const int s = rowptr[gwarp];
    const int t = rowptr[gwarp + 1];
    const float adv = (H == 4) ? ald[gwarp * 4 + head] : ald[gwarp];

    // pass 1: per-head max
    float m = -CUDART_INF_F;
    for (int i = s; i < t; i++) {
        int src = csr[i];
        float v = ((H == 4) ? als[src * 4 + head] : als[src]) + adv;
        v = v > 0.f ? v : NEG_SLOPE * v;
        m = fmaxf(m, v);
    }

    // pass 2: exp, denom, weighted gather-sum
    float den = 0.f;
    float4 acc = make_float4(0.f, 0.f, 0.f, 0.f);
    for (int i = s; i < t; i++) {
        int src = csr[i];
        float v = ((H == 4) ? als[src * 4 + head] : als[src]) + adv;
        v = v > 0.f ? v : NEG_SLOPE * v;
        float ex = __expf(v - m);
        den += ex;
        float4 hv = *(const float4*)(hbuf + (long long)src * DIM + c0);
        acc.x = fmaf(hv.x, ex, acc.x);
        acc.y = fmaf(hv.y, ex, acc.y);
        acc.z = fmaf(hv.z, ex, acc.z);
        acc.w = fmaf(hv.w, ex, acc.w);
    }

    const float inv = 1.f / (den + 1e-16f);
    const float4 b4 = *(const float4*)(bias + c0);
    float4 o;
    o.x = acc.x * inv + b4.x;
    o.y = acc.y * inv + b4.y;
    o.z = acc.z * inv + b4.z;
    o.w = acc.w * inv + b4.w;
    if (ELU) {
        o.x = o.x > 0.f ? o.x : expm1f(o.x);
        o.y = o.y > 0.f ? o.y : expm1f(o.y);
        o.z = o.z > 0.f ? o.z : expm1f(o.z);
        o.w = o.w > 0.f ? o.w : expm1f(o.w);
    }
    *(float4*)(out + (long long)gwarp * DIM + c0) = o;
}

// ---------------- launch ----------------
extern "C" void kernel_launch(void* const* d_in, const int* in_sizes, int n_in,
                              void* d_out, int out_size)
{
    const float* x   = (const float*)d_in[0];
    const int*   ei  = (const int*)d_in[1];     // int32 edge_index [2, E]
    const float* W1  = (const float*)d_in[2];
    const float* as1 = (const float*)d_in[3];
    const float* ad1 = (const float*)d_in[4];
    const float* b1  = (const float*)d_in[5];
    const float* W2  = (const float*)d_in[6];
    const float* as2 = (const float*)d_in[7];
    const float* ad2 = (const float*)d_in[8];
    const float* b2  = (const float*)d_in[9];
    float*       out = (float*)d_out;

    const int N  = in_sizes[0] / DIM;
    const int E  = in_sizes[1] / 2;
    const int EE = E + N;

    float *h, *out1, *als, *ald;
    int *deg, *rowptr, *fill, *csr;
    cudaGetSymbolAddress((void**)&h,      g_h);
    cudaGetSymbolAddress((void**)&out1,   g_out1);
    cudaGetSymbolAddress((void**)&als,    g_als);
    cudaGetSymbolAddress((void**)&ald,    g_ald);
    cudaGetSymbolAddress((void**)&deg,    g_deg);
    cudaGetSymbolAddress((void**)&rowptr, g_rowptr);
    cudaGetSymbolAddress((void**)&fill,   g_fill);
    cudaGetSymbolAddress((void**)&csr,    g_csr);

    const int TB = 256;

    // CSR build (graph shared by both layers)
    k_deg_init<<<(N + TB - 1) / TB, TB>>>(deg, N);
    k_deg<<<(E + TB - 1) / TB, TB>>>(ei, E, deg);
    k_scan<<<1, 1024>>>(deg, rowptr, fill, N);
    k_fill<<<(EE + TB - 1) / TB, TB>>>(ei, E, EE, fill, csr);

    dim3 gWarp((unsigned)(((long long)N * 32 + TB - 1) / TB));
    dim3 gGemm((N + 15) / 16);

    // layer 1 (H=4), output with bias + ELU
    k_gemm_al<4><<<gGemm, 128>>>(x, W1, as1, ad1, h, als, ald, N);
    k_aggregate<4, true><<<gWarp, TB>>>(rowptr, csr, als, ald, h, b1, out1, N);

    // layer 2 (H=1), output with bias
    k_gemm_al<1><<<gGemm, 128>>>(out1, W2, as2, ad2, h, als, ald, N);
    k_aggregate<1, false><<<gWarp, TB>>>(rowptr, csr, als, ald, h, b2, out, N);
}

// round 7
// speedup vs baseline: 1.5603x; 1.0469x over previous
#include <cuda_runtime.h>
#include <cuda_bf16.h>
#include <math_constants.h>

#define N_NODES 50000
#define N_EDGES 600000
#define EE_MAX  (N_NODES + N_EDGES)
#define DIM     128
#define HEADS   4
#define NEG_SLOPE 0.2f

// ---------------- scratch (static device globals) ----------------
__device__ float g_h    [(long long)N_NODES * DIM];
__device__ float g_out1 [(long long)N_NODES * DIM];
__device__ float g_als  [N_NODES * HEADS];
__device__ float g_ald  [N_NODES * HEADS];
__device__ int   g_deg  [N_NODES];
__device__ int   g_rowptr[N_NODES + 1];
__device__ int   g_fill [N_NODES];
__device__ int   g_csr  [EE_MAX];

// ---------------- packed fp32x2 helpers ----------------
__device__ __forceinline__ void ffma2(unsigned long long& acc, unsigned long long a,
                                      unsigned long long b)
{
    asm("fma.rn.f32x2 %0, %1, %2, %0;" : "+l"(acc) : "l"(a), "l"(b));
}
__device__ __forceinline__ unsigned long long splat2(float x)
{
    unsigned long long r;
    asm("mov.b64 %0, {%1, %1};" : "=l"(r) : "f"(x));
    return r;
}
__device__ __forceinline__ void unpack2(unsigned long long v, float& a, float& b)
{
    asm("mov.b64 {%0, %1}, %2;" : "=f"(a), "=f"(b) : "l"(v));
}

// ---------------- GEMM + fused attention-logit reduction ----------------
template<int H>
__global__ void __launch_bounds__(128) k_gemm_al(
    const float* __restrict__ X, const float* __restrict__ W,
    const float* __restrict__ a_s, const float* __restrict__ a_d,
    float* __restrict__ Hout, float* __restrict__ als, float* __restrict__ ald, int N)
{
    __shared__ float xs[16][DIM];
    const int tid = threadIdx.x;
    const int cg  = tid & 31;
    const int rs  = tid >> 5;
    const int c0  = cg * 4;
    const int n0  = blockIdx.x * 16;

    for (int idx = tid; idx < 16 * (DIM / 4); idx += 128) {
        int r  = idx >> 5;
        int cc = (idx & 31) * 4;
        int n  = n0 + r;
        float4 v = make_float4(0.f, 0.f, 0.f, 0.f);
        if (n < N) v = *(const float4*)(X + (long long)n * DIM + cc);
        *(float4*)&xs[r][cc] = v;
    }
    __syncthreads();

    unsigned long long acc[4][2];
    #pragma unroll
    for (int r = 0; r < 4; r++) { acc[r][0] = 0ull; acc[r][1] = 0ull; }

    #pragma unroll 4
    for (int k = 0; k < DIM; k += 4) {
        ulonglong2 w0 = *(const ulonglong2*)(W + (k + 0) * DIM + c0);
        ulonglong2 w1 = *(const ulonglong2*)(W + (k + 1) * DIM + c0);
        ulonglong2 w2 = *(const ulonglong2*)(W + (k + 2) * DIM + c0);
        ulonglong2 w3 = *(const ulonglong2*)(W + (k + 3) * DIM + c0);
        #pragma unroll
        for (int r = 0; r < 4; r++) {
            float4 xv = *(const float4*)&xs[rs * 4 + r][k];
            unsigned long long x0 = splat2(xv.x), x1 = splat2(xv.y);
            unsigned long long x2 = splat2(xv.z), x3 = splat2(xv.w);
            ffma2(acc[r][0], w0.x, x0); ffma2(acc[r][1], w0.y, x0);
            ffma2(acc[r][0], w1.x, x1); ffma2(acc[r][1], w1.y, x1);
            ffma2(acc[r][0], w2.x, x2); ffma2(acc[r][1], w2.y, x2);
            ffma2(acc[r][0], w3.x, x3); ffma2(acc[r][1], w3.y, x3);
        }
    }

    const float4 as4 = *(const float4*)(a_s + c0);
    const float4 ad4 = *(const float4*)(a_d + c0);

    #pragma unroll
    for (int r = 0; r < 4; r++) {
        int n = n0 + rs * 4 + r;
        float a0, a1, a2, a3;
        unpack2(acc[r][0], a0, a1);
        unpack2(acc[r][1], a2, a3);
        if (n < N) {
            float4 o = make_float4(a0, a1, a2, a3);
            *(float4*)(Hout + (long long)n * DIM + c0) = o;
        }
        float ss = a0 * as4.x + a1 * as4.y + a2 * as4.z + a3 * as4.w;
        float sd = a0 * ad4.x + a1 * ad4.y + a2 * ad4.z + a3 * ad4.w;
        #pragma unroll
        for (int o = (H == 4 ? 4 : 16); o > 0; o >>= 1) {
            ss += __shfl_xor_sync(0xffffffffu, ss, o);
            sd += __shfl_xor_sync(0xffffffffu, sd, o);
        }
        if (H == 4) {
            if ((cg & 7) == 0 && n < N) {
                int hh = cg >> 3;
                als[n * 4 + hh] = ss;
                ald[n * 4 + hh] = sd;
            }
        } else {
            if (cg == 0 && n < N) { als[n] = ss; ald[n] = sd; }
        }
    }
}

// ---------------- CSR build ----------------
__global__ void k_deg_init(int* __restrict__ deg, int N)
{
    int i = blockIdx.x * blockDim.x + threadIdx.x;
    if (i < N) deg[i] = 1;   // self-loop pre-counted
}
__global__ void k_deg(const int* __restrict__ ei, int E, int* __restrict__ deg)
{
    int e = blockIdx.x * blockDim.x + threadIdx.x;
    if (e < E) atomicAdd(&deg[ei[E + e]], 1);
}
__global__ void k_scan(const int* __restrict__ deg, int* __restrict__ rowptr,
                       int* __restrict__ fill, int N)
{
    __shared__ int ssum[1024];
    int t = threadIdx.x;
    int strip = (N + 1023) / 1024;
    int lo = t * strip, hi = min(lo + strip, N);
    int s = 0;
    for (int i = lo; i < hi; i++) s += deg[i];
    ssum[t] = s;
    __syncthreads();
    for (int off = 1; off < 1024; off <<= 1) {
        int v = (t >= off) ? ssum[t - off] : 0;
        __syncthreads();
        ssum[t] += v;
        __syncthreads();
    }
    int base = (t == 0) ? 0 : ssum[t - 1];
    for (int i = lo; i < hi; i++) { rowptr[i] = base; fill[i] = base; base += deg[i]; }
    if (t == 1023) rowptr[N] = ssum[1023];
}
__global__ void k_fill(const int* __restrict__ ei, int E, int EE,
                       int* __restrict__ fill, int* __restrict__ csr)
{
    int e = blockIdx.x * blockDim.x + threadIdx.x;
    if (e >= EE) return;
    int src, dst;
    if (e < E) { src = ei[e]; dst = ei[E + e]; } else { src = dst = e - E; }
    int pos = atomicAdd(&fill[dst], 1);
    csr[pos] = src;
}

// ---------------- fused gather aggregation ----------------
// One warp per destination node. Lane -> 4 channels (c0 = lane*4).
// Pass 1 (segment max) is lane-parallel within each head group.
template<int H, bool ELU>
__global__ void k_aggregate(const int* __restrict__ rowptr, const int* __restrict__ csr,
                            const float* __restrict__ als, const float* __restrict__ ald,
                            const float* __restrict__ hbuf, const float* __restrict__ bias,
                            float* __restrict__ out, int N)
{
    int gwarp = (blockIdx.x * blockDim.x + threadIdx.x) >> 5;
    if (gwarp >= N) return;
    const int lane = threadIdx.x & 31;
    const int head = (H == 4) ? (lane >> 3) : 0;
    const int c0   = lane * 4;

    const int s = rowptr[gwarp];
    const int t = rowptr[gwarp + 1];
    const float adv = (H == 4) ? ald[gwarp * 4 + head] : ald[gwarp];

    // ---- pass 1: per-head max, lanes stripe edges within head group ----
    const int GS  = (H == 4) ? 8 : 32;        // group size
    const int sub = (H == 4) ? (lane & 7) : lane;
    float m = -CUDART_INF_F;
    for (int i = s + sub; i < t; i += GS) {
        int src = csr[i];
        float v = ((H == 4) ? als[src * 4 + head] : als[src]) + adv;
        v = v > 0.f ? v : NEG_SLOPE * v;
        m = fmaxf(m, v);
    }
    #pragma unroll
    for (int o = 1; o < GS; o <<= 1)
        m = fmaxf(m, __shfl_xor_sync(0xffffffffu, m, o));

    // ---- pass 2: exp + denom + weighted gather-sum (unrolled x2 for MLP) ----
    float den = 0.f;
    float4 acc = make_float4(0.f, 0.f, 0.f, 0.f);
    int i = s;
    for (; i + 1 < t; i += 2) {
        int s0 = csr[i], s1 = csr[i + 1];
        float v0 = ((H == 4) ? als[s0 * 4 + head] : als[s0]) + adv;
        float v1 = ((H == 4) ? als[s1 * 4 + head] : als[s1]) + adv;
        v0 = v0 > 0.f ? v0 : NEG_SLOPE * v0;
        v1 = v1 > 0.f ? v1 : NEG_SLOPE * v1;
        float e0 = __expf(v0 - m);
        float e1 = __expf(v1 - m);
        float4 h0 = *(const float4*)(hbuf + (long long)s0 * DIM + c0);
        float4 h1 = *(const float4*)(hbuf + (long long)s1 * DIM + c0);
        den += e0 + e1;
        acc.x = fmaf(h0.x, e0, fmaf(h1.x, e1, acc.x));
        acc.y = fmaf(h0.y, e0, fmaf(h1.y, e1, acc.y));
        acc.z = fmaf(h0.z, e0, fmaf(h1.z, e1, acc.z));
        acc.w = fmaf(h0.w, e0, fmaf(h1.w, e1, acc.w));
    }
    if (i < t) {
        int s0 = csr[i];
        float v0 = ((H == 4) ? als[s0 * 4 + head] : als[s0]) + adv;
        v0 = v0 > 0.f ? v0 : NEG_SLOPE * v0;
        float e0 = __expf(v0 - m);
        float4 h0 = *(const float4*)(hbuf + (long long)s0 * DIM + c0);
        den += e0;
        acc.x = fmaf(h0.x, e0, acc.x);
        acc.y = fmaf(h0.y, e0, acc.y);
        acc.z = fmaf(h0.z, e0, acc.z);
        acc.w = fmaf(h0.w, e0, acc.w);
    }

    const float inv = 1.f / (den + 1e-16f);
    const float4 b4 = *(const float4*)(bias + c0);
    float4 o;
    o.x = acc.x * inv + b4.x;
    o.y = acc.y * inv + b4.y;
    o.z = acc.z * inv + b4.z;
    o.w = acc.w * inv + b4.w;
    if (ELU) {
        o.x = o.x > 0.f ? o.x : expm1f(o.x);
        o.y = o.y > 0.f ? o.y : expm1f(o.y);
        o.z = o.z > 0.f ? o.z : expm1f(o.z);
        o.w = o.w > 0.f ? o.w : expm1f(o.w);
    }
    *(float4*)(out + (long long)gwarp * DIM + c0) = o;
}

// ---------------- launch ----------------
extern "C" void kernel_launch(void* const* d_in, const int* in_sizes, int n_in,
                              void* d_out, int out_size)
{
    const float* x   = (const float*)d_in[0];
    const int*   ei  = (const int*)d_in[1];
    const float* W1  = (const float*)d_in[2];
    const float* as1 = (const float*)d_in[3];
    const float* ad1 = (const float*)d_in[4];
    const float* b1  = (const float*)d_in[5];
    const float* W2  = (const float*)d_in[6];
    const float* as2 = (const float*)d_in[7];
    const float* ad2 = (const float*)d_in[8];
    const float* b2  = (const float*)d_in[9];
    float*       out = (float*)d_out;

    const int N  = in_sizes[0] / DIM;
    const int E  = in_sizes[1] / 2;
    const int EE = E + N;

    float *h, *out1, *als, *ald;
    int *deg, *rowptr, *fill, *csr;
    cudaGetSymbolAddress((void**)&h,      g_h);
    cudaGetSymbolAddress((void**)&out1,   g_out1);
    cudaGetSymbolAddress((void**)&als,    g_als);
    cudaGetSymbolAddress((void**)&ald,    g_ald);
    cudaGetSymbolAddress((void**)&deg,    g_deg);
    cudaGetSymbolAddress((void**)&rowptr, g_rowptr);
    cudaGetSymbolAddress((void**)&fill,   g_fill);
    cudaGetSymbolAddress((void**)&csr,    g_csr);

    const int TB = 256;

    // CSR build (graph shared by both layers)
    k_deg_init<<<(N + TB - 1) / TB, TB>>>(deg, N);
    k_deg<<<(E + TB - 1) / TB, TB>>>(ei, E, deg);
    k_scan<<<1, 1024>>>(deg, rowptr, fill, N);
    k_fill<<<(EE + TB - 1) / TB, TB>>>(ei, E, EE, fill, csr);

    dim3 gWarp((unsigned)(((long long)N * 32 + TB - 1) / TB));
    dim3 gGemm((N + 15) / 16);

    // layer 1 (H=4)
    k_gemm_al<4><<<gGemm, 128>>>(x, W1, as1, ad1, h, als, ald, N);
    k_aggregate<4, true><<<gWarp, TB>>>(rowptr, csr, als, ald, h, b1, out1, N);

    // layer 2 (H=1)
    k_gemm_al<1><<<gGemm, 128>>>(out1, W2, as2, ad2, h, als, ald, N);
    k_aggregate<1, false><<<gWarp, TB>>>(rowptr, csr, als, ald, h, b2, out, N);
}

// round 8
// speedup vs baseline: 1.5996x; 1.0252x over previous
#include <cuda_runtime.h>
#include <cuda_bf16.h>
#include <math_constants.h>

#define N_NODES 50000
#define N_EDGES 600000
#define EE_MAX  (N_NODES + N_EDGES)
#define DIM     128
#define HEADS   4
#define NEG_SLOPE 0.2f

// ---------------- scratch (static device globals) ----------------
__device__ float g_h    [(long long)N_NODES * DIM];
__device__ float g_out1 [(long long)N_NODES * DIM];
__device__ float g_als  [N_NODES * HEADS];
__device__ float g_ald  [N_NODES * HEADS];
__device__ int   g_deg  [N_NODES];
__device__ int   g_rowptr[N_NODES + 1];
__device__ int   g_fill [N_NODES];
__device__ int   g_csr  [EE_MAX];

// ---------------- packed fp32x2 helpers ----------------
__device__ __forceinline__ void ffma2(unsigned long long& acc, unsigned long long a,
                                      unsigned long long b)
{
    asm("fma.rn.f32x2 %0, %1, %2, %0;" : "+l"(acc) : "l"(a), "l"(b));
}
__device__ __forceinline__ unsigned long long splat2(float x)
{
    unsigned long long r;
    asm("mov.b64 %0, {%1, %1};" : "=l"(r) : "f"(x));
    return r;
}
__device__ __forceinline__ void unpack2(unsigned long long v, float& a, float& b)
{
    asm("mov.b64 {%0, %1}, %2;" : "=f"(a), "=f"(b) : "l"(v));
}

// ---------------- GEMM + fused attention-logit reduction ----------------
template<int H>
__global__ void __launch_bounds__(128) k_gemm_al(
    const float* __restrict__ X, const float* __restrict__ W,
    const float* __restrict__ a_s, const float* __restrict__ a_d,
    float* __restrict__ Hout, float* __restrict__ als, float* __restrict__ ald, int N)
{
    __shared__ float xs[16][DIM];
    const int tid = threadIdx.x;
    const int cg  = tid & 31;
    const int rs  = tid >> 5;
    const int c0  = cg * 4;
    const int n0  = blockIdx.x * 16;

    for (int idx = tid; idx < 16 * (DIM / 4); idx += 128) {
        int r  = idx >> 5;
        int cc = (idx & 31) * 4;
        int n  = n0 + r;
        float4 v = make_float4(0.f, 0.f, 0.f, 0.f);
        if (n < N) v = *(const float4*)(X + (long long)n * DIM + cc);
        *(float4*)&xs[r][cc] = v;
    }
    __syncthreads();

    unsigned long long acc[4][2];
    #pragma unroll
    for (int r = 0; r < 4; r++) { acc[r][0] = 0ull; acc[r][1] = 0ull; }

    #pragma unroll 4
    for (int k = 0; k < DIM; k += 4) {
        ulonglong2 w0 = *(const ulonglong2*)(W + (k + 0) * DIM + c0);
        ulonglong2 w1 = *(const ulonglong2*)(W + (k + 1) * DIM + c0);
        ulonglong2 w2 = *(const ulonglong2*)(W + (k + 2) * DIM + c0);
        ulonglong2 w3 = *(const ulonglong2*)(W + (k + 3) * DIM + c0);
        #pragma unroll
        for (int r = 0; r < 4; r++) {
            float4 xv = *(const float4*)&xs[rs * 4 + r][k];
            unsigned long long x0 = splat2(xv.x), x1 = splat2(xv.y);
            unsigned long long x2 = splat2(xv.z), x3 = splat2(xv.w);
            ffma2(acc[r][0], w0.x, x0); ffma2(acc[r][1], w0.y, x0);
            ffma2(acc[r][0], w1.x, x1); ffma2(acc[r][1], w1.y, x1);
            ffma2(acc[r][0], w2.x, x2); ffma2(acc[r][1], w2.y, x2);
            ffma2(acc[r][0], w3.x, x3); ffma2(acc[r][1], w3.y, x3);
        }
    }

    const float4 as4 = *(const float4*)(a_s + c0);
    const float4 ad4 = *(const float4*)(a_d + c0);

    #pragma unroll
    for (int r = 0; r < 4; r++) {
        int n = n0 + rs * 4 + r;
        float a0, a1, a2, a3;
        unpack2(acc[r][0], a0, a1);
        unpack2(acc[r][1], a2, a3);
        if (n < N) {
            float4 o = make_float4(a0, a1, a2, a3);
            *(float4*)(Hout + (long long)n * DIM + c0) = o;
        }
        float ss = a0 * as4.x + a1 * as4.y + a2 * as4.z + a3 * as4.w;
        float sd = a0 * ad4.x + a1 * ad4.y + a2 * ad4.z + a3 * ad4.w;
        #pragma unroll
        for (int o = (H == 4 ? 4 : 16); o > 0; o >>= 1) {
            ss += __shfl_xor_sync(0xffffffffu, ss, o);
            sd += __shfl_xor_sync(0xffffffffu, sd, o);
        }
        if (H == 4) {
            if ((cg & 7) == 0 && n < N) {
                int hh = cg >> 3;
                als[n * 4 + hh] = ss;
                ald[n * 4 + hh] = sd;
            }
        } else {
            if (cg == 0 && n < N) { als[n] = ss; ald[n] = sd; }
        }
    }
}

// ---------------- CSR build ----------------
__global__ void k_deg_init(int* __restrict__ deg, int N)
{
    int i = blockIdx.x * blockDim.x + threadIdx.x;
    if (i < N) deg[i] = 1;   // self-loop pre-counted
}
// 4 edges per thread, int4 loads of dst
__global__ void k_deg(const int* __restrict__ ei, int E, int* __restrict__ deg)
{
    int e4 = (blockIdx.x * blockDim.x + threadIdx.x) * 4;
    const int* dsts = ei + E;
    if (e4 + 3 < E) {
        int4 d = *(const int4*)(dsts + e4);
        atomicAdd(&deg[d.x], 1);
        atomicAdd(&deg[d.y], 1);
        atomicAdd(&deg[d.z], 1);
        atomicAdd(&deg[d.w], 1);
    } else {
        for (int e = e4; e < E; e++) atomicAdd(&deg[dsts[e]], 1);
    }
}
// 1024-thread shuffle-based block scan over striped partial sums
__global__ void k_scan(const int* __restrict__ deg, int* __restrict__ rowptr,
                       int* __restrict__ fill, int N)
{
    __shared__ int wsum[32];
    const int t = threadIdx.x;
    const int strip = (N + 1023) / 1024;
    const int lo = t * strip, hi = min(lo + strip, N);
    int s = 0;
    for (int i = lo; i < hi; i++) s += deg[i];

    const int lane = t & 31, wid = t >> 5;
    int v = s;
    #pragma unroll
    for (int o = 1; o < 32; o <<= 1) {
        int u = __shfl_up_sync(0xffffffffu, v, o);
        if (lane >= o) v += u;
    }
    if (lane == 31) wsum[wid] = v;
    __syncthreads();
    if (wid == 0) {
        int w = wsum[lane];
        #pragma unroll
        for (int o = 1; o < 32; o <<= 1) {
            int u = __shfl_up_sync(0xffffffffu, w, o);
            if (lane >= o) w += u;
        }
        wsum[lane] = w;
    }
    __syncthreads();
    int incl = v + (wid > 0 ? wsum[wid - 1] : 0);
    int base = incl - s;
    for (int i = lo; i < hi; i++) { rowptr[i] = base; fill[i] = base; base += deg[i]; }
    if (t == 1023) rowptr[N] = incl;
}
// 4 edges per thread, int4 loads of src and dst
__global__ void k_fill(const int* __restrict__ ei, int E, int EE,
                       int* __restrict__ fill, int* __restrict__ csr)
{
    int e4 = (blockIdx.x * blockDim.x + threadIdx.x) * 4;
    if (e4 >= EE) return;
    if (e4 + 3 < E) {
        int4 s = *(const int4*)(ei + e4);
        int4 d = *(const int4*)(ei + E + e4);
        csr[atomicAdd(&fill[d.x], 1)] = s.x;
        csr[atomicAdd(&fill[d.y], 1)] = s.y;
        csr[atomicAdd(&fill[d.z], 1)] = s.z;
        csr[atomicAdd(&fill[d.w], 1)] = s.w;
    } else {
        for (int e = e4; e < min(e4 + 4, EE); e++) {
            int src, dst;
            if (e < E) { src = ei[e]; dst = ei[E + e]; } else { src = dst = e - E; }
            csr[atomicAdd(&fill[dst], 1)] = src;
        }
    }
}

// ---------------- fused single-pass gather aggregation ----------------
// One warp per destination node. Lane -> 4 channels (c0 = lane*4).
// No max-subtraction: logits are O(1), exp() is safe in fp32, and
// exp(v)/sum exp(v) is mathematically identical to the max-shifted form.
template<int H, bool ELU>
__global__ void k_aggregate(const int* __restrict__ rowptr, const int* __restrict__ csr,
                            const float* __restrict__ als, const float* __restrict__ ald,
                            const float* __restrict__ hbuf, const float* __restrict__ bias,
                            float* __restrict__ out, int N)
{
    int node = (blockIdx.x * blockDim.x + threadIdx.x) >> 5;
    if (node >= N) return;
    const int lane = threadIdx.x & 31;
    const int head = (H == 4) ? (lane >> 3) : 0;
    const int c0   = lane * 4;

    const int s = rowptr[node];
    const int t = rowptr[node + 1];
    const float adv = (H == 4) ? ald[node * 4 + head] : ald[node];

    float den = 0.f;
    float4 acc = make_float4(0.f, 0.f, 0.f, 0.f);

    int i = s;
    for (; i + 3 < t; i += 4) {
        int s0 = csr[i], s1 = csr[i + 1], s2 = csr[i + 2], s3 = csr[i + 3];
        float v0 = ((H == 4) ? als[s0 * 4 + head] : als[s0]) + adv;
        float v1 = ((H == 4) ? als[s1 * 4 + head] : als[s1]) + adv;
        float v2 = ((H == 4) ? als[s2 * 4 + head] : als[s2]) + adv;
        float v3 = ((H == 4) ? als[s3 * 4 + head] : als[s3]) + adv;
        v0 = v0 > 0.f ? v0 : NEG_SLOPE * v0;
        v1 = v1 > 0.f ? v1 : NEG_SLOPE * v1;
        v2 = v2 > 0.f ? v2 : NEG_SLOPE * v2;
        v3 = v3 > 0.f ? v3 : NEG_SLOPE * v3;
        float e0 = __expf(v0), e1 = __expf(v1), e2 = __expf(v2), e3 = __expf(v3);
        float4 h0 = *(const float4*)(hbuf + (long long)s0 * DIM + c0);
        float4 h1 = *(const float4*)(hbuf + (long long)s1 * DIM + c0);
        float4 h2 = *(const float4*)(hbuf + (long long)s2 * DIM + c0);
        float4 h3 = *(const float4*)(hbuf + (long long)s3 * DIM + c0);
        den += (e0 + e1) + (e2 + e3);
        acc.x = fmaf(h0.x, e0, fmaf(h1.x, e1, fmaf(h2.x, e2, fmaf(h3.x, e3, acc.x))));
        acc.y = fmaf(h0.y, e0, fmaf(h1.y, e1, fmaf(h2.y, e2, fmaf(h3.y, e3, acc.y))));
        acc.z = fmaf(h0.z, e0, fmaf(h1.z, e1, fmaf(h2.z, e2, fmaf(h3.z, e3, acc.z))));
        acc.w = fmaf(h0.w, e0, fmaf(h1.w, e1, fmaf(h2.w, e2, fmaf(h3.w, e3, acc.w))));
    }
    for (; i < t; i++) {
        int s0 = csr[i];
        float v0 = ((H == 4) ? als[s0 * 4 + head] : als[s0]) + adv;
        v0 = v0 > 0.f ? v0 : NEG_SLOPE * v0;
        float e0 = __expf(v0);
        float4 h0 = *(const float4*)(hbuf + (long long)s0 * DIM + c0);
        den += e0;
        acc.x = fmaf(h0.x, e0, acc.x);
        acc.y = fmaf(h0.y, e0, acc.y);
        acc.z = fmaf(h0.z, e0, acc.z);
        acc.w = fmaf(h0.w, e0, acc.w);
    }

    const float inv = 1.f / (den + 1e-16f);
    const float4 b4 = *(const float4*)(bias + c0);
    float4 o;
    o.x = acc.x * inv + b4.x;
    o.y = acc.y * inv + b4.y;
    o.z = acc.z * inv + b4.z;
    o.w = acc.w * inv + b4.w;
    if (ELU) {
        o.x = o.x > 0.f ? o.x : expm1f(o.x);
        o.y = o.y > 0.f ? o.y : expm1f(o.y);
        o.z = o.z > 0.f ? o.z : expm1f(o.z);
        o.w = o.w > 0.f ? o.w : expm1f(o.w);
    }
    *(float4*)(out + (long long)node * DIM + c0) = o;
}

// ---------------- launch ----------------
extern "C" void kernel_launch(void* const* d_in, const int* in_sizes, int n_in,
                              void* d_out, int out_size)
{
    const float* x   = (const float*)d_in[0];
    const int*   ei  = (const int*)d_in[1];
    const float* W1  = (const float*)d_in[2];
    const float* as1 = (const float*)d_in[3];
    const float* ad1 = (const float*)d_in[4];
    const float* b1  = (const float*)d_in[5];
    const float* W2  = (const float*)d_in[6];
    const float* as2 = (const float*)d_in[7];
    const float* ad2 = (const float*)d_in[8];
    const float* b2  = (const float*)d_in[9];
    float*       out = (float*)d_out;

    const int N  = in_sizes[0] / DIM;
    const int E  = in_sizes[1] / 2;
    const int EE = E + N;

    float *h, *out1, *als, *ald;
    int *deg, *rowptr, *fill, *csr;
    cudaGetSymbolAddress((void**)&h,      g_h);
    cudaGetSymbolAddress((void**)&out1,   g_out1);
    cudaGetSymbolAddress((void**)&als,    g_als);
    cudaGetSymbolAddress((void**)&ald,    g_ald);
    cudaGetSymbolAddress((void**)&deg,    g_deg);
    cudaGetSymbolAddress((void**)&rowptr, g_rowptr);
    cudaGetSymbolAddress((void**)&fill,   g_fill);
    cudaGetSymbolAddress((void**)&csr,    g_csr);

    const int TB = 256;

    // CSR build (graph shared by both layers)
    k_deg_init<<<(N + TB - 1) / TB, TB>>>(deg, N);
    k_deg<<<((E + 3) / 4 + TB - 1) / TB, TB>>>(ei, E, deg);
    k_scan<<<1, 1024>>>(deg, rowptr, fill, N);
    k_fill<<<((EE + 3) / 4 + TB - 1) / TB, TB>>>(ei, E, EE, fill, csr);

    dim3 gWarp((unsigned)(((long long)N * 32 + TB - 1) / TB));
    dim3 gGemm((N + 15) / 16);

    // layer 1 (H=4)
    k_gemm_al<4><<<gGemm, 128>>>(x, W1, as1, ad1, h, als, ald, N);
    k_aggregate<4, true><<<gWarp, TB>>>(rowptr, csr, als, ald, h, b1, out1, N);

    // layer 2 (H=1)
    k_gemm_al<1><<<gGemm, 128>>>(out1, W2, as2, ad2, h, als, ald, N);
    k_aggregate<1, false><<<gWarp, TB>>>(rowptr, csr, als, ald, h, b2, out, N);
}

// round 10
// speedup vs baseline: 1.6893x; 1.0561x over previous
#include <cuda_runtime.h>
#include <cuda_bf16.h>
#include <cuda_fp16.h>
#include <math_constants.h>

#define N_NODES 50000
#define N_EDGES 600000
#define EE_MAX  (N_NODES + N_EDGES)
#define DIM     128
#define HEADS   4
#define NEG_SLOPE 0.2f

// ---------------- scratch (static device globals) ----------------
__device__ __half g_h   [(long long)N_NODES * DIM];   // h = X @ W, fp16 (gather traffic halved)
__device__ float g_out1 [(long long)N_NODES * DIM];
__device__ float g_als  [N_NODES * HEADS];
__device__ float g_ald  [N_NODES * HEADS];
__device__ int   g_deg  [N_NODES];
__device__ int   g_rowptr[N_NODES + 1];
__device__ int   g_fill [N_NODES];
__device__ int   g_csr  [EE_MAX];

// ---------------- packed fp32x2 helpers ----------------
__device__ __forceinline__ void ffma2(unsigned long long& acc, unsigned long long a,
                                      unsigned long long b)
{
    asm("fma.rn.f32x2 %0, %1, %2, %0;" : "+l"(acc) : "l"(a), "l"(b));
}
__device__ __forceinline__ unsigned long long splat2(float x)
{
    unsigned long long r;
    asm("mov.b64 %0, {%1, %1};" : "=l"(r) : "f"(x));
    return r;
}
__device__ __forceinline__ void unpack2(unsigned long long v, float& a, float& b)
{
    asm("mov.b64 {%0, %1}, %2;" : "=f"(a), "=f"(b) : "l"(v));
}

// ---------------- GEMM + fused attention-logit reduction ----------------
// Block: 256 threads = 8 warps, covers 32 rows x 128 channels.
// Warp w handles rows w*4..w*4+3; lane -> 4 channels. Hout stored fp16;
// logits computed from fp32 accumulators (full precision).
template<int H>
__global__ void __launch_bounds__(256) k_gemm_al(
    const float* __restrict__ X, const float* __restrict__ W,
    const float* __restrict__ a_s, const float* __restrict__ a_d,
    __half* __restrict__ Hout, float* __restrict__ als, float* __restrict__ ald, int N)
{
    __shared__ float xs[32][DIM];
    const int tid = threadIdx.x;
    const int cg  = tid & 31;
    const int rs  = tid >> 5;          // warp id 0..7
    const int c0  = cg * 4;
    const int n0  = blockIdx.x * 32;

    for (int idx = tid; idx < 32 * (DIM / 4); idx += 256) {
        int r  = idx >> 5;             // 0..31
        int cc = (idx & 31) * 4;
        int n  = n0 + r;
        float4 v = make_float4(0.f, 0.f, 0.f, 0.f);
        if (n < N) v = *(const float4*)(X + (long long)n * DIM + cc);
        *(float4*)&xs[r][cc] = v;
    }
    __syncthreads();

    unsigned long long acc[4][2];
    #pragma unroll
    for (int r = 0; r < 4; r++) { acc[r][0] = 0ull; acc[r][1] = 0ull; }

    #pragma unroll 4
    for (int k = 0; k < DIM; k += 4) {
        ulonglong2 w0 = *(const ulonglong2*)(W + (k + 0) * DIM + c0);
        ulonglong2 w1 = *(const ulonglong2*)(W + (k + 1) * DIM + c0);
        ulonglong2 w2 = *(const ulonglong2*)(W + (k + 2) * DIM + c0);
        ulonglong2 w3 = *(const ulonglong2*)(W + (k + 3) * DIM + c0);
        #pragma unroll
        for (int r = 0; r < 4; r++) {
            float4 xv = *(const float4*)&xs[rs * 4 + r][k];
            unsigned long long x0 = splat2(xv.x), x1 = splat2(xv.y);
            unsigned long long x2 = splat2(xv.z), x3 = splat2(xv.w);
            ffma2(acc[r][0], w0.x, x0); ffma2(acc[r][1], w0.y, x0);
            ffma2(acc[r][0], w1.x, x1); ffma2(acc[r][1], w1.y, x1);
            ffma2(acc[r][0], w2.x, x2); ffma2(acc[r][1], w2.y, x2);
            ffma2(acc[r][0], w3.x, x3); ffma2(acc[r][1], w3.y, x3);
        }
    }

    const float4 as4 = *(const float4*)(a_s + c0);
    const float4 ad4 = *(const float4*)(a_d + c0);

    #pragma unroll
    for (int r = 0; r < 4; r++) {
        int n = n0 + rs * 4 + r;
        float a0, a1, a2, a3;
        unpack2(acc[r][0], a0, a1);
        unpack2(acc[r][1], a2, a3);
        if (n < N) {
            __half2 h01 = __floats2half2_rn(a0, a1);
            __half2 h23 = __floats2half2_rn(a2, a3);
            uint2 pk;
            pk.x = *reinterpret_cast<unsigned*>(&h01);
            pk.y = *reinterpret_cast<unsigned*>(&h23);
            *(uint2*)(Hout + (long long)n * DIM + c0) = pk;
        }
        float ss = a0 * as4.x + a1 * as4.y + a2 * as4.z + a3 * as4.w;
        float sd = a0 * ad4.x + a1 * ad4.y + a2 * ad4.z + a3 * ad4.w;
        #pragma unroll
        for (int o = (H == 4 ? 4 : 16); o > 0; o >>= 1) {
            ss += __shfl_xor_sync(0xffffffffu, ss, o);
            sd += __shfl_xor_sync(0xffffffffu, sd, o);
        }
        if (H == 4) {
            if ((cg & 7) == 0 && n < N) {
                int hh = cg >> 3;
                als[n * 4 + hh] = ss;
                ald[n * 4 + hh] = sd;
            }
        } else {
            if (cg == 0 && n < N) { als[n] = ss; ald[n] = sd; }
        }
    }
}

// ---------------- CSR build ----------------
__global__ void k_deg_init(int* __restrict__ deg, int N)
{
    int i = blockIdx.x * blockDim.x + threadIdx.x;
    if (i < N) deg[i] = 1;   // self-loop pre-counted
}
__global__ void k_deg(const int* __restrict__ ei, int E, int* __restrict__ deg)
{
    int e4 = (blockIdx.x * blockDim.x + threadIdx.x) * 4;
    const int* dsts = ei + E;
    if (e4 + 3 < E) {
        int4 d = *(const int4*)(dsts + e4);
        atomicAdd(&deg[d.x], 1);
        atomicAdd(&deg[d.y], 1);
        atomicAdd(&deg[d.z], 1);
        atomicAdd(&deg[d.w], 1);
    } else {
        for (int e = e4; e < E; e++) atomicAdd(&deg[dsts[e]], 1);
    }
}
__global__ void k_scan(const int* __restrict__ deg, int* __restrict__ rowptr,
                       int* __restrict__ fill, int N)
{
    __shared__ int wsum[32];
    const int t = threadIdx.x;
    const int strip = (N + 1023) / 1024;
    const int lo = t * strip, hi = min(lo + strip, N);
    int s = 0;
    #pragma unroll 4
    for (int i = lo; i < hi; i++) s += deg[i];

    const int lane = t & 31, wid = t >> 5;
    int v = s;
    #pragma unroll
    for (int o = 1; o < 32; o <<= 1) {
        int u = __shfl_up_sync(0xffffffffu, v, o);
        if (lane >= o) v += u;
    }
    if (lane == 31) wsum[wid] = v;
    __syncthreads();
    if (wid == 0) {
        int w = wsum[lane];
        #pragma unroll
        for (int o = 1; o < 32; o <<= 1) {
            int u = __shfl_up_sync(0xffffffffu, w, o);
            if (lane >= o) w += u;
        }
        wsum[lane] = w;
    }
    __syncthreads();
    int incl = v + (wid > 0 ? wsum[wid - 1] : 0);
    int base = incl - s;
    for (int i = lo; i < hi; i++) { rowptr[i] = base; fill[i] = base; base += deg[i]; }
    if (t == 1023) rowptr[N] = incl;
}
__global__ void k_fill(const int* __restrict__ ei, int E, int EE,
                       int* __restrict__ fill, int* __restrict__ csr)
{
    int e4 = (blockIdx.x * blockDim.x + threadIdx.x) * 4;
    if (e4 >= EE) return;
    if (e4 + 3 < E) {
        int4 s = *(const int4*)(ei + e4);
        int4 d = *(const int4*)(ei + E + e4);
        csr[atomicAdd(&fill[d.x], 1)] = s.x;
        csr[atomicAdd(&fill[d.y], 1)] = s.y;
        csr[atomicAdd(&fill[d.z], 1)] = s.z;
        csr[atomicAdd(&fill[d.w], 1)] = s.w;
    } else {
        for (int e = e4; e < min(e4 + 4, EE); e++) {
            int src, dst;
            if (e < E) { src = ei[e]; dst = ei[E + e]; } else { src = dst = e - E; }
            csr[atomicAdd(&fill[dst], 1)] = src;
        }
    }
}

// ---------------- fused single-pass gather aggregation ----------------
// One warp per destination node. Lane -> 4 channels (c0 = lane*4), h in fp16.
// No max-subtraction: logits are O(1); exp(v)/sum exp(v) identical to shifted form.
template<int H, bool ELU>
__global__ void k_aggregate(const int* __restrict__ rowptr, const int* __restrict__ csr,
                            const float* __restrict__ als, const float* __restrict__ ald,
                            const __half* __restrict__ hbuf, const float* __restrict__ bias,
                            float* __restrict__ out, int N)
{
    int node = (blockIdx.x * blockDim.x + threadIdx.x) >> 5;
    if (node >= N) return;
    const int lane = threadIdx.x & 31;
    const int head = (H == 4) ? (lane >> 3) : 0;
    const int c0   = lane * 4;

    const int s = rowptr[node];
    const int t = rowptr[node + 1];
    const float adv = (H == 4) ? ald[node * 4 + head] : ald[node];

    float den = 0.f;
    float4 acc = make_float4(0.f, 0.f, 0.f, 0.f);

    int i = s;
    for (; i + 3 < t; i += 4) {
        int s0 = csr[i], s1 = csr[i + 1], s2 = csr[i + 2], s3 = csr[i + 3];
        float v0 = ((H == 4) ? als[s0 * 4 + head] : als[s0]) + adv;
        float v1 = ((H == 4) ? als[s1 * 4 + head] : als[s1]) + adv;
        float v2 = ((H == 4) ? als[s2 * 4 + head] : als[s2]) + adv;
        float v3 = ((H == 4) ? als[s3 * 4 + head] : als[s3]) + adv;
        v0 = v0 > 0.f ? v0 : NEG_SLOPE * v0;
        v1 = v1 > 0.f ? v1 : NEG_SLOPE * v1;
        v2 = v2 > 0.f ? v2 : NEG_SLOPE * v2;
        v3 = v3 > 0.f ? v3 : NEG_SLOPE * v3;
        float e0 = __expf(v0), e1 = __expf(v1), e2 = __expf(v2), e3 = __expf(v3);
        uint2 u0 = *(const uint2*)(hbuf + (long long)s0 * DIM + c0);
        uint2 u1 = *(const uint2*)(hbuf + (long long)s1 * DIM + c0);
        uint2 u2 = *(const uint2*)(hbuf + (long long)s2 * DIM + c0);
        uint2 u3 = *(const uint2*)(hbuf + (long long)s3 * DIM + c0);
        den += (e0 + e1) + (e2 + e3);
        float2 f0a = __half22float2(*reinterpret_cast<const __half2*>(&u0.x));
        float2 f0b = __half22float2(*reinterpret_cast<const __half2*>(&u0.y));
        float2 f1a = __half22float2(*reinterpret_cast<const __half2*>(&u1.x));
        float2 f1b = __half22float2(*reinterpret_cast<const __half2*>(&u1.y));
        float2 f2a = __half22float2(*reinterpret_cast<const __half2*>(&u2.x));
        float2 f2b = __half22float2(*reinterpret_cast<const __half2*>(&u2.y));
        float2 f3a = __half22float2(*reinterpret_cast<const __half2*>(&u3.x));
        float2 f3b = __half22float2(*reinterpret_cast<const __half2*>(&u3.y));
        acc.x = fmaf(f0a.x, e0, fmaf(f1a.x, e1, fmaf(f2a.x, e2, fmaf(f3a.x, e3, acc.x))));
        acc.y = fmaf(f0a.y, e0, fmaf(f1a.y, e1, fmaf(f2a.y, e2, fmaf(f3a.y, e3, acc.y))));
        acc.z = fmaf(f0b.x, e0, fmaf(f1b.x, e1, fmaf(f2b.x, e2, fmaf(f3b.x, e3, acc.z))));
        acc.w = fmaf(f0b.y, e0, fmaf(f1b.y, e1, fmaf(f2b.y, e2, fmaf(f3b.y, e3, acc.w))));
    }
    for (; i < t; i++) {
        int s0 = csr[i];
        float v0 = ((H == 4) ? als[s0 * 4 + head] : als[s0]) + adv;
        v0 = v0 > 0.f ? v0 : NEG_SLOPE * v0;
        float e0 = __expf(v0);
        uint2 u0 = *(const uint2*)(hbuf + (long long)s0 * DIM + c0);
        float2 f0a = __half22float2(*reinterpret_cast<const __half2*>(&u0.x));
        float2 f0b = __half22float2(*reinterpret_cast<const __half2*>(&u0.y));
        den += e0;
        acc.x = fmaf(f0a.x, e0, acc.x);
        acc.y = fmaf(f0a.y, e0, acc.y);
        acc.z = fmaf(f0b.x, e0, acc.z);
        acc.w = fmaf(f0b.y, e0, acc.w);
    }

    const float inv = 1.f / (den + 1e-16f);
    const float4 b4 = *(const float4*)(bias + c0);
    float4 o;
    o.x = acc.x * inv + b4.x;
    o.y = acc.y * inv + b4.y;
    o.z = acc.z * inv + b4.z;
    o.w = acc.w * inv + b4.w;
    if (ELU) {
        o.x = o.x > 0.f ? o.x : expm1f(o.x);
        o.y = o.y > 0.f ? o.y : expm1f(o.y);
        o.z = o.z > 0.f ? o.z : expm1f(o.z);
        o.w = o.w > 0.f ? o.w : expm1f(o.w);
    }
    *(float4*)(out + (long long)node * DIM + c0) = o;
}

// ---------------- launch ----------------
extern "C" void kernel_launch(void* const* d_in, const int* in_sizes, int n_in,
                              void* d_out, int out_size)
{
    const float* x   = (const float*)d_in[0];
    const int*   ei  = (const int*)d_in[1];
    const float* W1  = (const float*)d_in[2];
    const float* as1 = (const float*)d_in[3];
    const float* ad1 = (const float*)d_in[4];
    const float* b1  = (const float*)d_in[5];
    const float* W2  = (const float*)d_in[6];
    const float* as2 = (const float*)d_in[7];
    const float* ad2 = (const float*)d_in[8];
    const float* b2  = (const float*)d_in[9];
    float*       out = (float*)d_out;

    const int N  = in_sizes[0] / DIM;
    const int E  = in_sizes[1] / 2;
    const int EE = E + N;

    __half* h;
    float *out1, *als, *ald;
    int *deg, *rowptr, *fill, *csr;
    cudaGetSymbolAddress((void**)&h,      g_h);
    cudaGetSymbolAddress((void**)&out1,   g_out1);
    cudaGetSymbolAddress((void**)&als,    g_als);
    cudaGetSymbolAddress((void**)&ald,    g_ald);
    cudaGetSymbolAddress((void**)&deg,    g_deg);
    cudaGetSymbolAddress((void**)&rowptr, g_rowptr);
    cudaGetSymbolAddress((void**)&fill,   g_fill);
    cudaGetSymbolAddress((void**)&csr,    g_csr);

    const int TB = 256;

    // CSR build (graph shared by both layers)
    k_deg_init<<<(N + TB - 1) / TB, TB>>>(deg, N);
    k_deg<<<((E + 3) / 4 + TB - 1) / TB, TB>>>(ei, E, deg);
    k_scan<<<1, 1024>>>(deg, rowptr, fill, N);
    k_fill<<<((EE + 3) / 4 + TB - 1) / TB, TB>>>(ei, E, EE, fill, csr);

    dim3 gWarp((unsigned)(((long long)N * 32 + TB - 1) / TB));
    dim3 gGemm((N + 31) / 32);

    // layer 1 (H=4)
    k_gemm_al<4><<<gGemm, 256>>>(x, W1, as1, ad1, h, als, ald, N);
    k_aggregate<4, true><<<gWarp, TB>>>(rowptr, csr, als, ald, h, b1, out1, N);

    // layer 2 (H=1)
    k_gemm_al<1><<<gGemm, 256>>>(out1, W2, as2, ad2, h, als, ald, N);
    k_aggregate<1, false><<<gWarp, TB>>>(rowptr, csr, als, ald, h, b2, out, N);
}